// round 14
// baseline (speedup 1.0000x reference)
#include <cuda_runtime.h>

#define NN 100000
#define EE 1600000
#define NPAD (98 * 1024)          // NN padded to scan granularity (98 blocks x 1024)
#define HGRID 592                 // persistent hop kernel: 148 SM x 4 blocks
#define HBLK  512

// Static device scratch (allocation-free per harness rules)
__device__ float g_rs[NN];        // staged value ns*r_k (gathered in scatter)
__device__ float g_acc[NN];       // edge-scatter accumulator
__device__ float g_ns[NN];        // out_deg^-1/2
__device__ float g_nd[NN];        // in_deg^-1/2
__device__ int2  g_edge[EE];      // (src, dst | rank<<17) in input order
__device__ __align__(16) int2 g_sort[EE];  // (src, dst) sorted by dst
__device__ int   g_cs[NPAD];      // src histogram (out-degree)
__device__ int   g_cd[NPAD];      // dst histogram (in-degree, sort key)
__device__ int   g_row[NPAD];     // exclusive scan of g_cd (CSR row starts)
__device__ int   g_part[98];      // per-block partial sums
__device__ int   g_tick;          // monotone ticket counter for k_scan
__device__ int   g_tick2;         // monotone ticket counter for hop barriers
__device__ float g_scal[8];       // s0..s5, w
__device__ int   g_is64;

#define DMASK 0x1FFFF             // low 17 bits: dst  (NN=100000 < 2^17)

// ---------------------------------------------------------------------------
// Fused setup: block 0 = collapse linear channel path to scalars; block 1 =
// index dtype probe (first 256 elems as u64: 2KB read, safe for either dtype;
// genuine int64 indices are all < NN, aliased int32 pairs exceed NN w.p. ~1);
// blocks 2.. = zero histograms + accumulator.
// ---------------------------------------------------------------------------
__global__ void k_setup(const unsigned long long* __restrict__ srcp,
                        const float* __restrict__ W0, const float* __restrict__ b0,
                        const float* __restrict__ W1, const float* __restrict__ b1,
                        const float* __restrict__ W2, const float* __restrict__ b2,
                        const float* __restrict__ W3, const float* __restrict__ b3,
                        const float* __restrict__ W4, const float* __restrict__ b4,
                        const float* __restrict__ W5, const float* __restrict__ b5) {
    int t = threadIdx.x;
    if (blockIdx.x == 0) {
        __shared__ float u5[32], u4[64], u3[128], u2[64], u1[32];
        if (t < 32) u5[t] = W5[t];
        __syncthreads();
        if (t < 64) { float s = 0.f; for (int j = 0; j < 32; j++) s += W4[t*32+j]*u5[j]; u4[t] = s; }
        __syncthreads();
        if (t < 128){ float s = 0.f; for (int j = 0; j < 64; j++) s += W3[t*64+j]*u4[j]; u3[t] = s; }
        __syncthreads();
        if (t < 64) { float s = 0.f; for (int j = 0; j < 128;j++) s += W2[t*128+j]*u3[j]; u2[t] = s; }
        __syncthreads();
        if (t < 32) { float s = 0.f; for (int j = 0; j < 64; j++) s += W1[t*64+j]*u2[j]; u1[t] = s; }
        __syncthreads();
        if (t == 0) {
            float w = 0.f, s0 = 0.f;
            for (int j = 0; j < 32; j++)  { w += W0[j]*u1[j]; s0 += b0[j]*u1[j]; }
            float s1 = 0.f; for (int j = 0; j < 64;  j++) s1 += b1[j]*u2[j];
            float s2 = 0.f; for (int j = 0; j < 128; j++) s2 += b2[j]*u3[j];
            float s3 = 0.f; for (int j = 0; j < 64;  j++) s3 += b3[j]*u4[j];
            float s4 = 0.f; for (int j = 0; j < 32;  j++) s4 += b4[j]*u5[j];
            g_scal[0]=s0; g_scal[1]=s1; g_scal[2]=s2; g_scal[3]=s3; g_scal[4]=s4;
            g_scal[5]=b5[0]; g_scal[6]=w;
        }
    } else if (blockIdx.x == 1) {
        int bad = (srcp[t] >= (unsigned long long)NN) ? 1 : 0;
        int any = __syncthreads_or(bad);
        if (t == 0) g_is64 = any ? 0 : 1;
    } else {
        int n = (blockIdx.x - 2) * blockDim.x + t;     // 0 .. NPAD/4-1
        if (n < NPAD / 4) {
            int4 zi = make_int4(0, 0, 0, 0);
            reinterpret_cast<int4*>(g_cs)[n] = zi;
            reinterpret_cast<int4*>(g_cd)[n] = zi;
            if (n < NN / 4)
                reinterpret_cast<float4*>(g_acc)[n] = make_float4(0.f, 0.f, 0.f, 0.f);
        }
    }
}

// Decode 1 edge/thread, clamp, histogram both endpoints. The dst atomic's
// RETURN VALUE is the edge's rank within its bucket — packed into the high
// bits next to dst so the permute needs no atomics.
__global__ void k_edges(const void* __restrict__ srcv,
                        const void* __restrict__ dstv) {
    int e = blockIdx.x * blockDim.x + threadIdx.x;
    if (e < EE) {
        long long sl, dl;
        if (g_is64) {
            sl = ((const long long*)srcv)[e];
            dl = ((const long long*)dstv)[e];
        } else {
            sl = ((const int*)srcv)[e];
            dl = ((const int*)dstv)[e];
        }
        int s = (sl < 0) ? 0 : (sl >= NN ? NN - 1 : (int)sl);
        int d = (dl < 0) ? 0 : (dl >= NN ? NN - 1 : (int)dl);
        atomicAdd(&g_cs[s], 1);
        int r = atomicAdd(&g_cd[d], 1);        // rank within dst bucket
        g_edge[e] = make_int2(s, d | (r << 17));
    }
}

// Fused full scan of g_cd -> g_row (exclusive offsets). 98 co-resident blocks
// with an internal monotone ticket barrier.
__global__ void k_scan() {
    int t = threadIdx.x, b = blockIdx.x;
    int4 c = reinterpret_cast<const int4*>(g_cd)[b * 256 + t];
    int tsum = c.x + c.y + c.z + c.w;

    __shared__ int sh[256];    // inclusive-scan workspace
    __shared__ int red[256];   // reduce workspace
    sh[t] = tsum;
    red[t] = tsum;
    __syncthreads();
    for (int off = 128; off > 0; off >>= 1) {
        if (t < off) red[t] += red[t + off];
        __syncthreads();
    }

    __shared__ int s_target;
    if (t == 0) {
        g_part[b] = red[0];
        __threadfence();
        int ticket = atomicAdd(&g_tick, 1);          // monotone across replays
        s_target = (ticket / 98 + 1) * 98;
        while ((*(volatile int*)&g_tick) - s_target < 0) { }
        __threadfence();
    }
    __syncthreads();

    // base_b = sum of g_part[j] for j < b  (volatile: other SMs wrote these)
    int pv = (t < b && t < 98) ? *(volatile int*)&g_part[t] : 0;
    red[t] = pv;
    __syncthreads();
    for (int off = 128; off > 0; off >>= 1) {
        if (t < off) red[t] += red[t + off];
        __syncthreads();
    }
    int base0 = red[0];

    // inclusive scan of tsum across the block
    for (int off = 1; off < 256; off <<= 1) {
        int a = (t >= off) ? sh[t - off] : 0;
        __syncthreads();
        sh[t] += a;
        __syncthreads();
    }
    int base = base0 + sh[t] - tsum;           // exclusive
    int4 o;
    o.x = base;
    o.y = o.x + c.x;
    o.z = o.y + c.y;
    o.w = o.z + c.z;
    reinterpret_cast<int4*>(g_row)[b * 256 + t] = o;
}

// Fused permute + init. Blocks [0, GE): place each edge at row[dst]+rank
// (no atomics). Blocks [GE, GE+98): finalize norms, stage rs0 = ns*w*x.
__global__ void k_permInit(int ge, const float* __restrict__ x) {
    if (blockIdx.x < (unsigned)ge) {
        int e = blockIdx.x * blockDim.x + threadIdx.x;
        if (e < EE) {
            int2 ed = g_edge[e];
            int d = ed.y & DMASK;
            int r = ((unsigned)ed.y) >> 17;
            g_sort[g_row[d] + r] = make_int2(ed.x, d);
        }
    } else {
        int n = (blockIdx.x - ge) * blockDim.x + threadIdx.x;
        if (n < NN / 4) {
            float w = g_scal[6];
            int4 cs = reinterpret_cast<const int4*>(g_cs)[n];
            int4 cd = reinterpret_cast<const int4*>(g_cd)[n];
            float4 xv = reinterpret_cast<const float4*>(x)[n];
            float4 ns, nd, rs;
            ns.x = rsqrtf(fmaxf((float)cs.x, 1.f)); nd.x = rsqrtf(fmaxf((float)cd.x, 1.f));
            ns.y = rsqrtf(fmaxf((float)cs.y, 1.f)); nd.y = rsqrtf(fmaxf((float)cd.y, 1.f));
            ns.z = rsqrtf(fmaxf((float)cs.z, 1.f)); nd.z = rsqrtf(fmaxf((float)cd.z, 1.f));
            ns.w = rsqrtf(fmaxf((float)cs.w, 1.f)); nd.w = rsqrtf(fmaxf((float)cd.w, 1.f));
            rs.x = ns.x * w * xv.x; rs.y = ns.y * w * xv.y;
            rs.z = ns.z * w * xv.z; rs.w = ns.w * w * xv.w;
            reinterpret_cast<float4*>(g_ns)[n] = ns;
            reinterpret_cast<float4*>(g_nd)[n] = nd;
            reinterpret_cast<float4*>(g_rs)[n] = rs;
        }
    }
}

// Device-wide barrier across the HGRID co-resident blocks (monotone ticket:
// each barrier consumes exactly HGRID tickets, so (t/HGRID+1)*HGRID is the
// release point; valid across graph replays since increments never reset).
__device__ __forceinline__ void hop_barrier() {
    __syncthreads();
    if (threadIdx.x == 0) {
        __threadfence();
        int ticket = atomicAdd(&g_tick2, 1);
        int target = (ticket / HGRID + 1) * HGRID;
        while ((*(volatile int*)&g_tick2) - target < 0) { }
        __threadfence();
    }
    __syncthreads();
}

// Persistent kernel: all 6 hops. Each hop = pair-aggregated segmented
// reduction over dst-sorted edges (grid-stride; warp handles 64 consecutive
// edges per iteration) + barrier + node-wise post (r_{k+1} = nd*acc + s_k;
// k<5 stages rs and re-zeroes acc; k==5 writes |r6| to out) + barrier.
__global__ void __launch_bounds__(HBLK, 4) k_hops(float* __restrict__ out) {
    const int tid = blockIdx.x * HBLK + threadIdx.x;
    const int T = HGRID * HBLK;
    const unsigned lane = threadIdx.x & 31;

    for (int k = 0; k < 6; k++) {
        // ---- scatter phase: pairs of edges, warp-segmented reduction ----
        for (int i = tid; i < EE / 2; i += T) {
            int4 q = reinterpret_cast<const int4*>(g_sort)[i];   // (s0,d0,s1,d1)
            float v0 = __ldg(&g_rs[q.x]);
            float v1 = __ldg(&g_rs[q.z]);
            int d0 = q.y, d1 = q.w;

            bool pairsame = (d0 == d1);
            float a = pairsame ? (v0 + v1) : v1;     // trailing-run contribution

            int d1prev = __shfl_up_sync(0xFFFFFFFFu, d1, 1);
            int d0next = __shfl_down_sync(0xFFFFFFFFu, d0, 1);

            bool head = (lane == 0) || (d1prev != d1) || !pairsame;
            unsigned hm = __ballot_sync(0xFFFFFFFFu, head);
            unsigned below = hm & ((2u << lane) - 1u);
            int start = 31 - __clz(below);

#pragma unroll
            for (int off = 1; off < 32; off <<= 1) {
                float u = __shfl_up_sync(0xFFFFFFFFu, a, off);
                if ((int)lane - off >= start) a += u;
            }
            float aprev = __shfl_up_sync(0xFFFFFFFFu, a, 1);

            if (!pairsame) {
                float sum0 = v0;
                if (lane > 0 && d1prev == d0) sum0 += aprev;
                atomicAdd(&g_acc[d0], sum0);
            }
            bool tail = (lane == 31) || (d0next != d1);
            if (tail) atomicAdd(&g_acc[d1], a);
        }

        hop_barrier();

        // ---- post phase: node-wise update (float4) ----
        float sk = g_scal[k];
        for (int n = tid; n < NN / 4; n += T) {
            float4 nd = reinterpret_cast<float4*>(g_nd)[n];
            float4 ac = reinterpret_cast<float4*>(g_acc)[n];
            float4 v;
            v.x = nd.x * ac.x + sk;
            v.y = nd.y * ac.y + sk;
            v.z = nd.z * ac.z + sk;
            v.w = nd.w * ac.w + sk;
            if (k == 5) {
                float4 o;
                o.x = fabsf(v.x); o.y = fabsf(v.y);
                o.z = fabsf(v.z); o.w = fabsf(v.w);
                reinterpret_cast<float4*>(out)[n] = o;
            } else {
                float4 ns = reinterpret_cast<float4*>(g_ns)[n];
                float4 rs;
                rs.x = ns.x * v.x; rs.y = ns.y * v.y;
                rs.z = ns.z * v.z; rs.w = ns.w * v.w;
                reinterpret_cast<float4*>(g_rs)[n] = rs;
                reinterpret_cast<float4*>(g_acc)[n] = make_float4(0.f, 0.f, 0.f, 0.f);
            }
        }

        if (k < 5) hop_barrier();
    }
}

extern "C" void kernel_launch(void* const* d_in, const int* in_sizes, int n_in,
                              void* d_out, int out_size) {
    // Layout A (dict order): x, src, dst, W0,b0..W5,b5
    // Layout B (sorted):     W0..W5, b0..b5, dst, src, x
    const float *x, *W0, *b0, *W1, *b1, *W2, *b2, *W3, *b3, *W4, *b4, *W5, *b5;
    const void *src, *dst;

    if (in_sizes[0] == NN) {
        x   = (const float*)d_in[0];
        src = d_in[1];
        dst = d_in[2];
        W0 = (const float*)d_in[3];  b0 = (const float*)d_in[4];
        W1 = (const float*)d_in[5];  b1 = (const float*)d_in[6];
        W2 = (const float*)d_in[7];  b2 = (const float*)d_in[8];
        W3 = (const float*)d_in[9];  b3 = (const float*)d_in[10];
        W4 = (const float*)d_in[11]; b4 = (const float*)d_in[12];
        W5 = (const float*)d_in[13]; b5 = (const float*)d_in[14];
    } else {
        W0 = (const float*)d_in[0];  W1 = (const float*)d_in[1];
        W2 = (const float*)d_in[2];  W3 = (const float*)d_in[3];
        W4 = (const float*)d_in[4];  W5 = (const float*)d_in[5];
        b0 = (const float*)d_in[6];  b1 = (const float*)d_in[7];
        b2 = (const float*)d_in[8];  b3 = (const float*)d_in[9];
        b4 = (const float*)d_in[10]; b5 = (const float*)d_in[11];
        dst = d_in[12];
        src = d_in[13];
        x   = (const float*)d_in[14];
    }
    float* out = (float*)d_out;

    const int TB  = 256;
    const int GZ  = NPAD / 4 / TB + 2;            // setup: 98 zero blocks + 2
    const int GN4 = (NN / 4 + TB - 1) / TB;       // 98
    const int GE  = (EE + TB - 1) / TB;           // 6250

    k_setup<<<GZ, TB>>>((const unsigned long long*)src,
                        W0, b0, W1, b1, W2, b2, W3, b3, W4, b4, W5, b5);
    k_edges<<<GE, TB>>>(src, dst);
    k_scan<<<98, TB>>>();
    k_permInit<<<GE + GN4, TB>>>(GE, x);
    k_hops<<<HGRID, HBLK>>>(out);
}

// round 15
// speedup vs baseline: 1.0174x; 1.0174x over previous
#include <cuda_runtime.h>

#define NN 100000
#define EE 1600000
#define NPAD (98 * 1024)          // NN padded to scan granularity (98 blocks x 1024)

// Static device scratch (allocation-free per harness rules)
__device__ float g_rs[NN];        // staged value ns*r_k (gathered in scatter)
__device__ float g_acc[NN];       // edge-scatter accumulator
__device__ float g_ns[NN];        // out_deg^-1/2
__device__ float g_nd[NN];        // in_deg^-1/2
__device__ int2  g_edge[EE];      // (src, dst | rank<<17) in input order
__device__ __align__(16) int2 g_sort[EE];  // (src, dst) sorted by dst
__device__ int   g_cs[NPAD];      // src histogram (out-degree)
__device__ int   g_cd[NPAD];      // dst histogram (in-degree, sort key); pad stays 0
__device__ int   g_row[NPAD];     // exclusive scan of g_cd (CSR row starts)
__device__ int   g_part[98];      // per-block partial sums
__device__ int   g_tick;          // monotone ticket counter for scan barrier
__device__ int   g_epoch;         // replay counter (incremented in k_setup)
__device__ int   g_scandone;      // monotone: +98 per completed scan
__device__ float g_scal[8];       // s0..s5, w
__device__ int   g_is64;

#define DMASK 0x1FFFF             // low 17 bits: dst  (NN=100000 < 2^17)

// ---------------------------------------------------------------------------
// Fused setup: block 0 = collapse linear channel path to scalars + epoch++;
// block 1 = index dtype probe (first 256 elems as u64: 2KB read, safe for
// either dtype; genuine int64 indices are all < NN, aliased int32 pairs
// exceed NN w.p. ~1); blocks 2.. = zero histograms [0,NN) + accumulator.
// ---------------------------------------------------------------------------
__global__ void k_setup(const unsigned long long* __restrict__ srcp,
                        const float* __restrict__ W0, const float* __restrict__ b0,
                        const float* __restrict__ W1, const float* __restrict__ b1,
                        const float* __restrict__ W2, const float* __restrict__ b2,
                        const float* __restrict__ W3, const float* __restrict__ b3,
                        const float* __restrict__ W4, const float* __restrict__ b4,
                        const float* __restrict__ W5, const float* __restrict__ b5) {
    int t = threadIdx.x;
    if (blockIdx.x == 0) {
        __shared__ float u5[32], u4[64], u3[128], u2[64], u1[32];
        if (t < 32) u5[t] = W5[t];
        __syncthreads();
        if (t < 64) { float s = 0.f; for (int j = 0; j < 32; j++) s += W4[t*32+j]*u5[j]; u4[t] = s; }
        __syncthreads();
        if (t < 128){ float s = 0.f; for (int j = 0; j < 64; j++) s += W3[t*64+j]*u4[j]; u3[t] = s; }
        __syncthreads();
        if (t < 64) { float s = 0.f; for (int j = 0; j < 128;j++) s += W2[t*128+j]*u3[j]; u2[t] = s; }
        __syncthreads();
        if (t < 32) { float s = 0.f; for (int j = 0; j < 64; j++) s += W1[t*64+j]*u2[j]; u1[t] = s; }
        __syncthreads();
        if (t == 0) {
            float w = 0.f, s0 = 0.f;
            for (int j = 0; j < 32; j++)  { w += W0[j]*u1[j]; s0 += b0[j]*u1[j]; }
            float s1 = 0.f; for (int j = 0; j < 64;  j++) s1 += b1[j]*u2[j];
            float s2 = 0.f; for (int j = 0; j < 128; j++) s2 += b2[j]*u3[j];
            float s3 = 0.f; for (int j = 0; j < 64;  j++) s3 += b3[j]*u4[j];
            float s4 = 0.f; for (int j = 0; j < 32;  j++) s4 += b4[j]*u5[j];
            g_scal[0]=s0; g_scal[1]=s1; g_scal[2]=s2; g_scal[3]=s3; g_scal[4]=s4;
            g_scal[5]=b5[0]; g_scal[6]=w;
            atomicAdd(&g_epoch, 1);                     // once per replay
        }
    } else if (blockIdx.x == 1) {
        int bad = (srcp[t] >= (unsigned long long)NN) ? 1 : 0;
        int any = __syncthreads_or(bad);
        if (t == 0) g_is64 = any ? 0 : 1;
    } else {
        int n = (blockIdx.x - 2) * blockDim.x + t;     // zero [0, NN)
        if (n < NN / 4) {
            int4 zi = make_int4(0, 0, 0, 0);
            reinterpret_cast<int4*>(g_cs)[n] = zi;
            reinterpret_cast<int4*>(g_cd)[n] = zi;
            reinterpret_cast<float4*>(g_acc)[n] = make_float4(0.f, 0.f, 0.f, 0.f);
        }
    }
}

// Decode 1 edge/thread, clamp, histogram both endpoints. The dst atomic's
// RETURN VALUE is the edge's rank within its bucket — packed into the high
// bits next to dst so the permute needs no atomics.
__global__ void k_edges(const void* __restrict__ srcv,
                        const void* __restrict__ dstv) {
    int e = blockIdx.x * blockDim.x + threadIdx.x;
    if (e < EE) {
        long long sl, dl;
        if (g_is64) {
            sl = ((const long long*)srcv)[e];
            dl = ((const long long*)dstv)[e];
        } else {
            sl = ((const int*)srcv)[e];
            dl = ((const int*)dstv)[e];
        }
        int s = (sl < 0) ? 0 : (sl >= NN ? NN - 1 : (int)sl);
        int d = (dl < 0) ? 0 : (dl >= NN ? NN - 1 : (int)dl);
        atomicAdd(&g_cs[s], 1);
        int r = atomicAdd(&g_cd[d], 1);        // rank within dst bucket
        g_edge[e] = make_int2(s, d | (r << 17));
    }
}

// ---------------------------------------------------------------------------
// Fused scan + init + permute (one launch).
//   blocks [0,98):       full scan of g_cd -> g_row (ticket barrier among the
//                        98 co-resident scan blocks), then g_scandone += 1 each.
//   blocks [98,196):     init — finalize norms, stage rs0 = ns*w*x (needs only
//                        histograms; ungated).
//   blocks [196,196+GE): permute — spin until g_scandone >= 98*epoch, then
//                        place each edge at row[dst]+rank (no atomics).
// Scan blocks are FIRST so they're guaranteed into wave 1 (no deadlock).
// ---------------------------------------------------------------------------
__global__ void k_sortInit(const float* __restrict__ x) {
    int t = threadIdx.x;
    int b = blockIdx.x;

    if (b < 98) {
        // ---- scan ----
        int4 c = reinterpret_cast<const int4*>(g_cd)[b * 256 + t];
        int tsum = c.x + c.y + c.z + c.w;

        __shared__ int sh[256];
        __shared__ int red[256];
        sh[t] = tsum;
        red[t] = tsum;
        __syncthreads();
        for (int off = 128; off > 0; off >>= 1) {
            if (t < off) red[t] += red[t + off];
            __syncthreads();
        }

        __shared__ int s_dummy;
        if (t == 0) {
            g_part[b] = red[0];
            __threadfence();
            int ticket = atomicAdd(&g_tick, 1);        // monotone across replays
            int target = (ticket / 98 + 1) * 98;
            while ((*(volatile int*)&g_tick) - target < 0) { }
            __threadfence();
            s_dummy = 1;
        }
        __syncthreads();

        int pv = (t < b) ? *(volatile int*)&g_part[t] : 0;
        red[t] = pv;
        __syncthreads();
        for (int off = 128; off > 0; off >>= 1) {
            if (t < off) red[t] += red[t + off];
            __syncthreads();
        }
        int base0 = red[0];

        for (int off = 1; off < 256; off <<= 1) {
            int a = (t >= off) ? sh[t - off] : 0;
            __syncthreads();
            sh[t] += a;
            __syncthreads();
        }
        int base = base0 + sh[t] - tsum;
        int4 o;
        o.x = base;
        o.y = o.x + c.x;
        o.z = o.y + c.y;
        o.w = o.z + c.z;
        reinterpret_cast<int4*>(g_row)[b * 256 + t] = o;

        __syncthreads();
        if (t == 0) {
            __threadfence();
            atomicAdd(&g_scandone, 1);                 // 98 per replay
        }
        (void)s_dummy;
    } else if (b < 196) {
        // ---- init (norms + rs0) ----
        int n = (b - 98) * blockDim.x + t;
        if (n < NN / 4) {
            float w = g_scal[6];
            int4 cs = reinterpret_cast<const int4*>(g_cs)[n];
            int4 cd = reinterpret_cast<const int4*>(g_cd)[n];
            float4 xv = reinterpret_cast<const float4*>(x)[n];
            float4 ns, nd, rs;
            ns.x = rsqrtf(fmaxf((float)cs.x, 1.f)); nd.x = rsqrtf(fmaxf((float)cd.x, 1.f));
            ns.y = rsqrtf(fmaxf((float)cs.y, 1.f)); nd.y = rsqrtf(fmaxf((float)cd.y, 1.f));
            ns.z = rsqrtf(fmaxf((float)cs.z, 1.f)); nd.z = rsqrtf(fmaxf((float)cd.z, 1.f));
            ns.w = rsqrtf(fmaxf((float)cs.w, 1.f)); nd.w = rsqrtf(fmaxf((float)cd.w, 1.f));
            rs.x = ns.x * w * xv.x; rs.y = ns.y * w * xv.y;
            rs.z = ns.z * w * xv.z; rs.w = ns.w * w * xv.w;
            reinterpret_cast<float4*>(g_ns)[n] = ns;
            reinterpret_cast<float4*>(g_nd)[n] = nd;
            reinterpret_cast<float4*>(g_rs)[n] = rs;
        }
    } else {
        // ---- permute (gated on scan completion) ----
        __shared__ int s_go;
        if (t == 0) {
            int need = 98 * (*(volatile int*)&g_epoch);
            while ((*(volatile int*)&g_scandone) - need < 0) { }
            __threadfence();
            s_go = 1;
        }
        __syncthreads();
        (void)s_go;

        int e = (b - 196) * blockDim.x + t;
        if (e < EE) {
            int2 ed = g_edge[e];
            int d = ed.y & DMASK;
            int r = ((unsigned)ed.y) >> 17;
            g_sort[g_row[d] + r] = make_int2(ed.x, d);
        }
    }
}

// One propagation hop: 2 edges/thread pair-aggregated segmented reduction
// (R12-proven). dst-sorted ⇒ per pair d0<=d1 and prev.d1 <= d0. The 5-step
// shfl scan covers 64 edges per warp; mid-pair run breaks flush v0+prefix;
// run tails flush the scanned sum. ~150K atomics total.
__global__ void k_scatter() {
    int i = blockIdx.x * blockDim.x + threadIdx.x;
    if (i >= EE / 2) return;
    int4 q = reinterpret_cast<const int4*>(g_sort)[i];   // (s0,d0,s1,d1)
    float v0 = __ldg(&g_rs[q.x]);
    float v1 = __ldg(&g_rs[q.z]);
    int d0 = q.y, d1 = q.w;
    unsigned lane = threadIdx.x & 31;

    bool pairsame = (d0 == d1);
    float a = pairsame ? (v0 + v1) : v1;     // trailing-run (d1) contribution

    int d1prev = __shfl_up_sync(0xFFFFFFFFu, d1, 1);
    int d0next = __shfl_down_sync(0xFFFFFFFFu, d0, 1);

    bool head = (lane == 0) || (d1prev != d1) || !pairsame;
    unsigned hm = __ballot_sync(0xFFFFFFFFu, head);
    unsigned below = hm & ((2u << lane) - 1u);
    int start = 31 - __clz(below);

#pragma unroll
    for (int off = 1; off < 32; off <<= 1) {
        float u = __shfl_up_sync(0xFFFFFFFFu, a, off);
        if ((int)lane - off >= start) a += u;
    }
    float aprev = __shfl_up_sync(0xFFFFFFFFu, a, 1);

    if (!pairsame) {
        float sum0 = v0;
        if (lane > 0 && d1prev == d0) sum0 += aprev;
        atomicAdd(&g_acc[d0], sum0);
    }
    bool tail = (lane == 31) || (d0next != d1);
    if (tail) atomicAdd(&g_acc[d1], a);
}

// r_{k+1} = nd*acc + s_k. k<5: stage rs = ns*r_{k+1}, re-zero acc.
// k==5: out = |r_6|. (float4; TB=128 for more block-level parallelism)
__global__ void k_post(int k, float* __restrict__ out) {
    int n = blockIdx.x * blockDim.x + threadIdx.x;
    if (n < NN / 4) {
        float sk = g_scal[k];
        float4 nd = reinterpret_cast<float4*>(g_nd)[n];
        float4 ac = reinterpret_cast<float4*>(g_acc)[n];
        float4 v;
        v.x = nd.x * ac.x + sk;
        v.y = nd.y * ac.y + sk;
        v.z = nd.z * ac.z + sk;
        v.w = nd.w * ac.w + sk;
        if (k == 5) {
            float4 o;
            o.x = fabsf(v.x); o.y = fabsf(v.y);
            o.z = fabsf(v.z); o.w = fabsf(v.w);
            reinterpret_cast<float4*>(out)[n] = o;
        } else {
            float4 ns = reinterpret_cast<float4*>(g_ns)[n];
            float4 rs;
            rs.x = ns.x * v.x; rs.y = ns.y * v.y;
            rs.z = ns.z * v.z; rs.w = ns.w * v.w;
            reinterpret_cast<float4*>(g_rs)[n] = rs;
            reinterpret_cast<float4*>(g_acc)[n] = make_float4(0.f, 0.f, 0.f, 0.f);
        }
    }
}

extern "C" void kernel_launch(void* const* d_in, const int* in_sizes, int n_in,
                              void* d_out, int out_size) {
    // Layout A (dict order): x, src, dst, W0,b0..W5,b5
    // Layout B (sorted):     W0..W5, b0..b5, dst, src, x
    const float *x, *W0, *b0, *W1, *b1, *W2, *b2, *W3, *b3, *W4, *b4, *W5, *b5;
    const void *src, *dst;

    if (in_sizes[0] == NN) {
        x   = (const float*)d_in[0];
        src = d_in[1];
        dst = d_in[2];
        W0 = (const float*)d_in[3];  b0 = (const float*)d_in[4];
        W1 = (const float*)d_in[5];  b1 = (const float*)d_in[6];
        W2 = (const float*)d_in[7];  b2 = (const float*)d_in[8];
        W3 = (const float*)d_in[9];  b3 = (const float*)d_in[10];
        W4 = (const float*)d_in[11]; b4 = (const float*)d_in[12];
        W5 = (const float*)d_in[13]; b5 = (const float*)d_in[14];
    } else {
        W0 = (const float*)d_in[0];  W1 = (const float*)d_in[1];
        W2 = (const float*)d_in[2];  W3 = (const float*)d_in[3];
        W4 = (const float*)d_in[4];  W5 = (const float*)d_in[5];
        b0 = (const float*)d_in[6];  b1 = (const float*)d_in[7];
        b2 = (const float*)d_in[8];  b3 = (const float*)d_in[9];
        b4 = (const float*)d_in[10]; b5 = (const float*)d_in[11];
        dst = d_in[12];
        src = d_in[13];
        x   = (const float*)d_in[14];
    }
    float* out = (float*)d_out;

    const int TB  = 256;
    const int GZ  = (NN / 4 + TB - 1) / TB + 2;   // setup: 98 zero blocks + 2
    const int GE  = (EE + TB - 1) / TB;           // 6250
    const int GS2 = (EE / 2 + TB - 1) / TB;       // 3125
    const int GP  = (NN / 4 + 127) / 128;         // 196 post blocks (TB=128)

    k_setup<<<GZ, TB>>>((const unsigned long long*)src,
                        W0, b0, W1, b1, W2, b2, W3, b3, W4, b4, W5, b5);
    k_edges<<<GE, TB>>>(src, dst);
    k_sortInit<<<196 + GE, TB>>>(x);

    for (int k = 0; k < 6; k++) {
        k_scatter<<<GS2, TB>>>();
        k_post<<<GP, 128>>>(k, out);
    }
}

// round 16
// speedup vs baseline: 1.0460x; 1.0281x over previous
#include <cuda_runtime.h>

#define NN 100000
#define EE 1600000
#define NPAD (98 * 1024)          // NN padded to scan granularity (98 blocks x 1024)

// Static device scratch (allocation-free per harness rules)
__device__ float g_rs[NN];        // staged value ns*r_k (gathered in scatter)
__device__ float g_acc[NN];       // edge-scatter accumulator
__device__ float g_ns[NN];        // out_deg^-1/2
__device__ float g_nd[NN];        // in_deg^-1/2
__device__ int2  g_edge[EE];      // (src, dst | rank<<17) in input order
__device__ __align__(16) int2 g_sort[EE];  // (src, dst) sorted by dst
__device__ int   g_cs[NPAD];      // src histogram (out-degree)
__device__ int   g_cd[NPAD];      // dst histogram (in-degree, sort key)
__device__ int   g_row[NPAD];     // exclusive scan of g_cd (CSR row starts)
__device__ int   g_part[98];      // per-block partial sums
__device__ int   g_tick;          // monotone ticket counter (never reset)
__device__ float g_scal[8];       // s0..s5, w
__device__ int   g_is64;

#define DMASK 0x1FFFF             // low 17 bits: dst  (NN=100000 < 2^17)

// ---------------------------------------------------------------------------
// Fused setup: block 0 = collapse linear channel path to scalars; block 1 =
// index dtype probe (first 256 elems as u64: 2KB read, safe for either dtype;
// genuine int64 indices are all < NN, aliased int32 pairs exceed NN w.p. ~1);
// blocks 2.. = zero histograms + accumulator.
// ---------------------------------------------------------------------------
__global__ void k_setup(const unsigned long long* __restrict__ srcp,
                        const float* __restrict__ W0, const float* __restrict__ b0,
                        const float* __restrict__ W1, const float* __restrict__ b1,
                        const float* __restrict__ W2, const float* __restrict__ b2,
                        const float* __restrict__ W3, const float* __restrict__ b3,
                        const float* __restrict__ W4, const float* __restrict__ b4,
                        const float* __restrict__ W5, const float* __restrict__ b5) {
    int t = threadIdx.x;
    if (blockIdx.x == 0) {
        __shared__ float u5[32], u4[64], u3[128], u2[64], u1[32];
        if (t < 32) u5[t] = W5[t];
        __syncthreads();
        if (t < 64) { float s = 0.f; for (int j = 0; j < 32; j++) s += W4[t*32+j]*u5[j]; u4[t] = s; }
        __syncthreads();
        if (t < 128){ float s = 0.f; for (int j = 0; j < 64; j++) s += W3[t*64+j]*u4[j]; u3[t] = s; }
        __syncthreads();
        if (t < 64) { float s = 0.f; for (int j = 0; j < 128;j++) s += W2[t*128+j]*u3[j]; u2[t] = s; }
        __syncthreads();
        if (t < 32) { float s = 0.f; for (int j = 0; j < 64; j++) s += W1[t*64+j]*u2[j]; u1[t] = s; }
        __syncthreads();
        if (t == 0) {
            float w = 0.f, s0 = 0.f;
            for (int j = 0; j < 32; j++)  { w += W0[j]*u1[j]; s0 += b0[j]*u1[j]; }
            float s1 = 0.f; for (int j = 0; j < 64;  j++) s1 += b1[j]*u2[j];
            float s2 = 0.f; for (int j = 0; j < 128; j++) s2 += b2[j]*u3[j];
            float s3 = 0.f; for (int j = 0; j < 64;  j++) s3 += b3[j]*u4[j];
            float s4 = 0.f; for (int j = 0; j < 32;  j++) s4 += b4[j]*u5[j];
            g_scal[0]=s0; g_scal[1]=s1; g_scal[2]=s2; g_scal[3]=s3; g_scal[4]=s4;
            g_scal[5]=b5[0]; g_scal[6]=w;
        }
    } else if (blockIdx.x == 1) {
        int bad = (srcp[t] >= (unsigned long long)NN) ? 1 : 0;
        int any = __syncthreads_or(bad);
        if (t == 0) g_is64 = any ? 0 : 1;
    } else {
        int n = (blockIdx.x - 2) * blockDim.x + t;     // 0 .. NPAD/4-1
        if (n < NPAD / 4) {
            int4 zi = make_int4(0, 0, 0, 0);
            reinterpret_cast<int4*>(g_cs)[n] = zi;
            reinterpret_cast<int4*>(g_cd)[n] = zi;
            if (n < NN / 4)
                reinterpret_cast<float4*>(g_acc)[n] = make_float4(0.f, 0.f, 0.f, 0.f);
        }
    }
}

// Decode 1 edge/thread, clamp, histogram both endpoints. The dst atomic's
// RETURN VALUE is the edge's rank within its bucket — packed into the high
// bits next to dst so the permute needs no atomics.
__global__ void k_edges(const void* __restrict__ srcv,
                        const void* __restrict__ dstv) {
    int e = blockIdx.x * blockDim.x + threadIdx.x;
    if (e < EE) {
        long long sl, dl;
        if (g_is64) {
            sl = ((const long long*)srcv)[e];
            dl = ((const long long*)dstv)[e];
        } else {
            sl = ((const int*)srcv)[e];
            dl = ((const int*)dstv)[e];
        }
        int s = (sl < 0) ? 0 : (sl >= NN ? NN - 1 : (int)sl);
        int d = (dl < 0) ? 0 : (dl >= NN ? NN - 1 : (int)dl);
        atomicAdd(&g_cs[s], 1);
        int r = atomicAdd(&g_cd[d], 1);        // rank within dst bucket
        g_edge[e] = make_int2(s, d | (r << 17));
    }
}

// Fused full scan of g_cd -> g_row (exclusive offsets). 98 co-resident blocks
// with an internal monotone ticket barrier.
__global__ void k_scan() {
    int t = threadIdx.x, b = blockIdx.x;
    int4 c = reinterpret_cast<const int4*>(g_cd)[b * 256 + t];
    int tsum = c.x + c.y + c.z + c.w;

    __shared__ int sh[256];    // inclusive-scan workspace
    __shared__ int red[256];   // reduce workspace
    sh[t] = tsum;
    red[t] = tsum;
    __syncthreads();
    for (int off = 128; off > 0; off >>= 1) {
        if (t < off) red[t] += red[t + off];
        __syncthreads();
    }

    __shared__ int s_target;
    if (t == 0) {
        g_part[b] = red[0];
        __threadfence();
        int ticket = atomicAdd(&g_tick, 1);          // monotone across replays
        s_target = (ticket / 98 + 1) * 98;
        while ((*(volatile int*)&g_tick) - s_target < 0) { }
        __threadfence();
    }
    __syncthreads();

    // base_b = sum of g_part[j] for j < b  (volatile: other SMs wrote these)
    int pv = (t < b && t < 98) ? *(volatile int*)&g_part[t] : 0;
    red[t] = pv;
    __syncthreads();
    for (int off = 128; off > 0; off >>= 1) {
        if (t < off) red[t] += red[t + off];
        __syncthreads();
    }
    int base0 = red[0];

    // inclusive scan of tsum across the block
    for (int off = 1; off < 256; off <<= 1) {
        int a = (t >= off) ? sh[t - off] : 0;
        __syncthreads();
        sh[t] += a;
        __syncthreads();
    }
    int base = base0 + sh[t] - tsum;           // exclusive
    int4 o;
    o.x = base;
    o.y = o.x + c.x;
    o.z = o.y + c.y;
    o.w = o.z + c.z;
    reinterpret_cast<int4*>(g_row)[b * 256 + t] = o;
}

// Fused permute + init. Blocks [0, GE): place each edge at row[dst]+rank
// (no atomics). Blocks [GE, GE+98): finalize norms, stage rs0 = ns*w*x.
__global__ void k_permInit(int ge, const float* __restrict__ x) {
    if (blockIdx.x < (unsigned)ge) {
        int e = blockIdx.x * blockDim.x + threadIdx.x;
        if (e < EE) {
            int2 ed = g_edge[e];
            int d = ed.y & DMASK;
            int r = ((unsigned)ed.y) >> 17;
            g_sort[g_row[d] + r] = make_int2(ed.x, d);
        }
    } else {
        int n = (blockIdx.x - ge) * blockDim.x + threadIdx.x;
        if (n < NN / 4) {
            float w = g_scal[6];
            int4 cs = reinterpret_cast<const int4*>(g_cs)[n];
            int4 cd = reinterpret_cast<const int4*>(g_cd)[n];
            float4 xv = reinterpret_cast<const float4*>(x)[n];
            float4 ns, nd, rs;
            ns.x = rsqrtf(fmaxf((float)cs.x, 1.f)); nd.x = rsqrtf(fmaxf((float)cd.x, 1.f));
            ns.y = rsqrtf(fmaxf((float)cs.y, 1.f)); nd.y = rsqrtf(fmaxf((float)cd.y, 1.f));
            ns.z = rsqrtf(fmaxf((float)cs.z, 1.f)); nd.z = rsqrtf(fmaxf((float)cd.z, 1.f));
            ns.w = rsqrtf(fmaxf((float)cs.w, 1.f)); nd.w = rsqrtf(fmaxf((float)cd.w, 1.f));
            rs.x = ns.x * w * xv.x; rs.y = ns.y * w * xv.y;
            rs.z = ns.z * w * xv.z; rs.w = ns.w * w * xv.w;
            reinterpret_cast<float4*>(g_ns)[n] = ns;
            reinterpret_cast<float4*>(g_nd)[n] = nd;
            reinterpret_cast<float4*>(g_rs)[n] = rs;
        }
    }
}

// One propagation hop: 2 edges/thread pair-aggregated segmented reduction.
// dst-sorted ⇒ per pair d0<=d1 and prev.d1 <= d0. The 5-step shfl scan covers
// 64 edges per warp. Mid-pair run breaks (d0!=d1) flush v0 + neighbor prefix;
// run tails flush the scanned sum. ~150K atomics total.
__global__ void k_scatter() {
    int i = blockIdx.x * blockDim.x + threadIdx.x;
    if (i >= EE / 2) return;
    int4 q = reinterpret_cast<const int4*>(g_sort)[i];   // (s0,d0,s1,d1)
    float v0 = __ldg(&g_rs[q.x]);
    float v1 = __ldg(&g_rs[q.z]);
    int d0 = q.y, d1 = q.w;
    unsigned lane = threadIdx.x & 31;

    bool pairsame = (d0 == d1);
    float a = pairsame ? (v0 + v1) : v1;     // trailing-run (d1) contribution

    int d1prev = __shfl_up_sync(0xFFFFFFFFu, d1, 1);
    int d0next = __shfl_down_sync(0xFFFFFFFFu, d0, 1);

    bool head = (lane == 0) || (d1prev != d1) || !pairsame;
    unsigned hm = __ballot_sync(0xFFFFFFFFu, head);
    unsigned below = hm & ((2u << lane) - 1u);
    int start = 31 - __clz(below);

#pragma unroll
    for (int off = 1; off < 32; off <<= 1) {
        float u = __shfl_up_sync(0xFFFFFFFFu, a, off);
        if ((int)lane - off >= start) a += u;
    }
    float aprev = __shfl_up_sync(0xFFFFFFFFu, a, 1);

    if (!pairsame) {
        float sum0 = v0;
        if (lane > 0 && d1prev == d0) sum0 += aprev;
        atomicAdd(&g_acc[d0], sum0);
    }
    bool tail = (lane == 31) || (d0next != d1);
    if (tail) atomicAdd(&g_acc[d1], a);
}

// r_{k+1} = nd*acc + s_k. k<5: stage rs = ns*r_{k+1}, re-zero acc.
// k==5: out = |r_6|. (float4; TB=128 -> 196 blocks span all SMs)
__global__ void k_post(int k, float* __restrict__ out) {
    int n = blockIdx.x * blockDim.x + threadIdx.x;
    if (n < NN / 4) {
        float sk = g_scal[k];
        float4 nd = reinterpret_cast<float4*>(g_nd)[n];
        float4 ac = reinterpret_cast<float4*>(g_acc)[n];
        float4 v;
        v.x = nd.x * ac.x + sk;
        v.y = nd.y * ac.y + sk;
        v.z = nd.z * ac.z + sk;
        v.w = nd.w * ac.w + sk;
        if (k == 5) {
            float4 o;
            o.x = fabsf(v.x); o.y = fabsf(v.y);
            o.z = fabsf(v.z); o.w = fabsf(v.w);
            reinterpret_cast<float4*>(out)[n] = o;
        } else {
            float4 ns = reinterpret_cast<float4*>(g_ns)[n];
            float4 rs;
            rs.x = ns.x * v.x; rs.y = ns.y * v.y;
            rs.z = ns.z * v.z; rs.w = ns.w * v.w;
            reinterpret_cast<float4*>(g_rs)[n] = rs;
            reinterpret_cast<float4*>(g_acc)[n] = make_float4(0.f, 0.f, 0.f, 0.f);
        }
    }
}

extern "C" void kernel_launch(void* const* d_in, const int* in_sizes, int n_in,
                              void* d_out, int out_size) {
    // Layout A (dict order): x, src, dst, W0,b0..W5,b5
    // Layout B (sorted):     W0..W5, b0..b5, dst, src, x
    const float *x, *W0, *b0, *W1, *b1, *W2, *b2, *W3, *b3, *W4, *b4, *W5, *b5;
    const void *src, *dst;

    if (in_sizes[0] == NN) {
        x   = (const float*)d_in[0];
        src = d_in[1];
        dst = d_in[2];
        W0 = (const float*)d_in[3];  b0 = (const float*)d_in[4];
        W1 = (const float*)d_in[5];  b1 = (const float*)d_in[6];
        W2 = (const float*)d_in[7];  b2 = (const float*)d_in[8];
        W3 = (const float*)d_in[9];  b3 = (const float*)d_in[10];
        W4 = (const float*)d_in[11]; b4 = (const float*)d_in[12];
        W5 = (const float*)d_in[13]; b5 = (const float*)d_in[14];
    } else {
        W0 = (const float*)d_in[0];  W1 = (const float*)d_in[1];
        W2 = (const float*)d_in[2];  W3 = (const float*)d_in[3];
        W4 = (const float*)d_in[4];  W5 = (const float*)d_in[5];
        b0 = (const float*)d_in[6];  b1 = (const float*)d_in[7];
        b2 = (const float*)d_in[8];  b3 = (const float*)d_in[9];
        b4 = (const float*)d_in[10]; b5 = (const float*)d_in[11];
        dst = d_in[12];
        src = d_in[13];
        x   = (const float*)d_in[14];
    }
    float* out = (float*)d_out;

    const int TB  = 256;
    const int GZ  = NPAD / 4 / TB + 2;            // setup: 98 zero blocks + 2
    const int GN4 = (NN / 4 + TB - 1) / TB;       // 98
    const int GE  = (EE + TB - 1) / TB;           // 6250
    const int GS2 = (EE / 2 + TB - 1) / TB;       // 3125
    const int GP  = (NN / 4 + 127) / 128;         // 196 post blocks (TB=128)

    k_setup<<<GZ, TB>>>((const unsigned long long*)src,
                        W0, b0, W1, b1, W2, b2, W3, b3, W4, b4, W5, b5);
    k_edges<<<GE, TB>>>(src, dst);
    k_scan<<<98, TB>>>();
    k_permInit<<<GE + GN4, TB>>>(GE, x);

    for (int k = 0; k < 6; k++) {
        k_scatter<<<GS2, TB>>>();
        k_post<<<GP, 128>>>(k, out);
    }
}

// round 17
// speedup vs baseline: 1.0666x; 1.0197x over previous
#include <cuda_runtime.h>

#define NN 100000
#define EE 1600000
#define NPAD (98 * 1024)          // NN padded to scan granularity (98 blocks x 1024)

// Static device scratch (allocation-free per harness rules)
__device__ float g_rs[NN];        // staged value ns*r_k (gathered in scatter)
__device__ float g_acc[NN];       // edge-scatter accumulator
__device__ float g_ns[NN];        // out_deg^-1/2
__device__ float g_nd[NN];        // in_deg^-1/2
__device__ int2  g_edge[EE];      // (src, dst | rank<<17) in input order
__device__ __align__(16) int2 g_sort[EE];  // (src, dst) sorted by dst
__device__ int   g_cs[NPAD];      // src histogram (out-degree)
__device__ int   g_cd[NPAD];      // dst histogram (in-degree, sort key)
__device__ int   g_row[NPAD];     // exclusive scan of g_cd (CSR row starts)
__device__ int   g_part[98];      // per-block partial sums
__device__ int   g_tick;          // monotone ticket counter (never reset)
__device__ float g_scal[8];       // s0..s5, w
__device__ int   g_is64;

#define DMASK 0x1FFFF             // low 17 bits: dst  (NN=100000 < 2^17)

// ---------------------------------------------------------------------------
// Fused setup: block 0 = collapse linear channel path to scalars; block 1 =
// index dtype probe (first 256 elems as u64: 2KB read, safe for either dtype;
// genuine int64 indices are all < NN, aliased int32 pairs exceed NN w.p. ~1);
// blocks 2.. = zero histograms + accumulator.
// ---------------------------------------------------------------------------
__global__ void k_setup(const unsigned long long* __restrict__ srcp,
                        const float* __restrict__ W0, const float* __restrict__ b0,
                        const float* __restrict__ W1, const float* __restrict__ b1,
                        const float* __restrict__ W2, const float* __restrict__ b2,
                        const float* __restrict__ W3, const float* __restrict__ b3,
                        const float* __restrict__ W4, const float* __restrict__ b4,
                        const float* __restrict__ W5, const float* __restrict__ b5) {
    int t = threadIdx.x;
    if (blockIdx.x == 0) {
        __shared__ float u5[32], u4[64], u3[128], u2[64], u1[32];
        if (t < 32) u5[t] = W5[t];
        __syncthreads();
        if (t < 64) { float s = 0.f; for (int j = 0; j < 32; j++) s += W4[t*32+j]*u5[j]; u4[t] = s; }
        __syncthreads();
        if (t < 128){ float s = 0.f; for (int j = 0; j < 64; j++) s += W3[t*64+j]*u4[j]; u3[t] = s; }
        __syncthreads();
        if (t < 64) { float s = 0.f; for (int j = 0; j < 128;j++) s += W2[t*128+j]*u3[j]; u2[t] = s; }
        __syncthreads();
        if (t < 32) { float s = 0.f; for (int j = 0; j < 64; j++) s += W1[t*64+j]*u2[j]; u1[t] = s; }
        __syncthreads();
        if (t == 0) {
            float w = 0.f, s0 = 0.f;
            for (int j = 0; j < 32; j++)  { w += W0[j]*u1[j]; s0 += b0[j]*u1[j]; }
            float s1 = 0.f; for (int j = 0; j < 64;  j++) s1 += b1[j]*u2[j];
            float s2 = 0.f; for (int j = 0; j < 128; j++) s2 += b2[j]*u3[j];
            float s3 = 0.f; for (int j = 0; j < 64;  j++) s3 += b3[j]*u4[j];
            float s4 = 0.f; for (int j = 0; j < 32;  j++) s4 += b4[j]*u5[j];
            g_scal[0]=s0; g_scal[1]=s1; g_scal[2]=s2; g_scal[3]=s3; g_scal[4]=s4;
            g_scal[5]=b5[0]; g_scal[6]=w;
        }
    } else if (blockIdx.x == 1) {
        int bad = (srcp[t] >= (unsigned long long)NN) ? 1 : 0;
        int any = __syncthreads_or(bad);
        if (t == 0) g_is64 = any ? 0 : 1;
    } else {
        int n = (blockIdx.x - 2) * blockDim.x + t;     // 0 .. NPAD/4-1
        if (n < NPAD / 4) {
            int4 zi = make_int4(0, 0, 0, 0);
            reinterpret_cast<int4*>(g_cs)[n] = zi;
            reinterpret_cast<int4*>(g_cd)[n] = zi;
            if (n < NN / 4)
                reinterpret_cast<float4*>(g_acc)[n] = make_float4(0.f, 0.f, 0.f, 0.f);
        }
    }
}

// Decode 1 edge/thread, clamp, histogram both endpoints. The dst atomic's
// RETURN VALUE is the edge's rank within its bucket — packed into the high
// bits next to dst so the permute needs no atomics.
__global__ void k_edges(const void* __restrict__ srcv,
                        const void* __restrict__ dstv) {
    int e = blockIdx.x * blockDim.x + threadIdx.x;
    if (e < EE) {
        long long sl, dl;
        if (g_is64) {
            sl = ((const long long*)srcv)[e];
            dl = ((const long long*)dstv)[e];
        } else {
            sl = ((const int*)srcv)[e];
            dl = ((const int*)dstv)[e];
        }
        int s = (sl < 0) ? 0 : (sl >= NN ? NN - 1 : (int)sl);
        int d = (dl < 0) ? 0 : (dl >= NN ? NN - 1 : (int)dl);
        atomicAdd(&g_cs[s], 1);
        int r = atomicAdd(&g_cd[d], 1);        // rank within dst bucket
        g_edge[e] = make_int2(s, d | (r << 17));
    }
}

// Fused full scan of g_cd -> g_row (exclusive offsets). 98 co-resident blocks
// with an internal monotone ticket barrier.
__global__ void k_scan() {
    int t = threadIdx.x, b = blockIdx.x;
    int4 c = reinterpret_cast<const int4*>(g_cd)[b * 256 + t];
    int tsum = c.x + c.y + c.z + c.w;

    __shared__ int sh[256];    // inclusive-scan workspace
    __shared__ int red[256];   // reduce workspace
    sh[t] = tsum;
    red[t] = tsum;
    __syncthreads();
    for (int off = 128; off > 0; off >>= 1) {
        if (t < off) red[t] += red[t + off];
        __syncthreads();
    }

    __shared__ int s_target;
    if (t == 0) {
        g_part[b] = red[0];
        __threadfence();
        int ticket = atomicAdd(&g_tick, 1);          // monotone across replays
        s_target = (ticket / 98 + 1) * 98;
        while ((*(volatile int*)&g_tick) - s_target < 0) { }
        __threadfence();
    }
    __syncthreads();

    // base_b = sum of g_part[j] for j < b  (volatile: other SMs wrote these)
    int pv = (t < b && t < 98) ? *(volatile int*)&g_part[t] : 0;
    red[t] = pv;
    __syncthreads();
    for (int off = 128; off > 0; off >>= 1) {
        if (t < off) red[t] += red[t + off];
        __syncthreads();
    }
    int base0 = red[0];

    // inclusive scan of tsum across the block
    for (int off = 1; off < 256; off <<= 1) {
        int a = (t >= off) ? sh[t - off] : 0;
        __syncthreads();
        sh[t] += a;
        __syncthreads();
    }
    int base = base0 + sh[t] - tsum;           // exclusive
    int4 o;
    o.x = base;
    o.y = o.x + c.x;
    o.z = o.y + c.y;
    o.w = o.z + c.z;
    reinterpret_cast<int4*>(g_row)[b * 256 + t] = o;
}

// Fused permute + init. Blocks [0, GE): place each edge at row[dst]+rank
// (no atomics). Blocks [GE, GE+98): finalize norms, stage rs0 = ns*w*x.
__global__ void k_permInit(int ge, const float* __restrict__ x) {
    if (blockIdx.x < (unsigned)ge) {
        int e = blockIdx.x * blockDim.x + threadIdx.x;
        if (e < EE) {
            int2 ed = g_edge[e];
            int d = ed.y & DMASK;
            int r = ((unsigned)ed.y) >> 17;
            g_sort[g_row[d] + r] = make_int2(ed.x, d);
        }
    } else {
        int n = (blockIdx.x - ge) * blockDim.x + threadIdx.x;
        if (n < NN / 4) {
            float w = g_scal[6];
            int4 cs = reinterpret_cast<const int4*>(g_cs)[n];
            int4 cd = reinterpret_cast<const int4*>(g_cd)[n];
            float4 xv = reinterpret_cast<const float4*>(x)[n];
            float4 ns, nd, rs;
            ns.x = rsqrtf(fmaxf((float)cs.x, 1.f)); nd.x = rsqrtf(fmaxf((float)cd.x, 1.f));
            ns.y = rsqrtf(fmaxf((float)cs.y, 1.f)); nd.y = rsqrtf(fmaxf((float)cd.y, 1.f));
            ns.z = rsqrtf(fmaxf((float)cs.z, 1.f)); nd.z = rsqrtf(fmaxf((float)cd.z, 1.f));
            ns.w = rsqrtf(fmaxf((float)cs.w, 1.f)); nd.w = rsqrtf(fmaxf((float)cd.w, 1.f));
            rs.x = ns.x * w * xv.x; rs.y = ns.y * w * xv.y;
            rs.z = ns.z * w * xv.z; rs.w = ns.w * w * xv.w;
            reinterpret_cast<float4*>(g_ns)[n] = ns;
            reinterpret_cast<float4*>(g_nd)[n] = nd;
            reinterpret_cast<float4*>(g_rs)[n] = rs;
        }
    }
}

// One propagation hop: 2 edges/thread pair-aggregated segmented reduction.
// dst-sorted ⇒ per pair d0<=d1 and prev.d1 <= d0. The 5-step shfl scan covers
// 64 edges per warp. Mid-pair run breaks (d0!=d1) flush v0 + neighbor prefix;
// run tails flush the scanned sum. ~150K atomics total.
__global__ void k_scatter() {
    int i = blockIdx.x * blockDim.x + threadIdx.x;
    if (i >= EE / 2) return;
    int4 q = reinterpret_cast<const int4*>(g_sort)[i];   // (s0,d0,s1,d1)
    float v0 = __ldg(&g_rs[q.x]);
    float v1 = __ldg(&g_rs[q.z]);
    int d0 = q.y, d1 = q.w;
    unsigned lane = threadIdx.x & 31;

    bool pairsame = (d0 == d1);
    float a = pairsame ? (v0 + v1) : v1;     // trailing-run (d1) contribution

    int d1prev = __shfl_up_sync(0xFFFFFFFFu, d1, 1);
    int d0next = __shfl_down_sync(0xFFFFFFFFu, d0, 1);

    bool head = (lane == 0) || (d1prev != d1) || !pairsame;
    unsigned hm = __ballot_sync(0xFFFFFFFFu, head);
    unsigned below = hm & ((2u << lane) - 1u);
    int start = 31 - __clz(below);

#pragma unroll
    for (int off = 1; off < 32; off <<= 1) {
        float u = __shfl_up_sync(0xFFFFFFFFu, a, off);
        if ((int)lane - off >= start) a += u;
    }
    float aprev = __shfl_up_sync(0xFFFFFFFFu, a, 1);

    if (!pairsame) {
        float sum0 = v0;
        if (lane > 0 && d1prev == d0) sum0 += aprev;
        atomicAdd(&g_acc[d0], sum0);
    }
    bool tail = (lane == 31) || (d0next != d1);
    if (tail) atomicAdd(&g_acc[d1], a);
}

// r_{k+1} = nd*acc + s_k. k<5: stage rs = ns*r_{k+1}, re-zero acc.
// k==5: out = |r_6|. (float4)
__global__ void k_post(int k, float* __restrict__ out) {
    int n = blockIdx.x * blockDim.x + threadIdx.x;
    if (n < NN / 4) {
        float sk = g_scal[k];
        float4 nd = reinterpret_cast<float4*>(g_nd)[n];
        float4 ac = reinterpret_cast<float4*>(g_acc)[n];
        float4 v;
        v.x = nd.x * ac.x + sk;
        v.y = nd.y * ac.y + sk;
        v.z = nd.z * ac.z + sk;
        v.w = nd.w * ac.w + sk;
        if (k == 5) {
            float4 o;
            o.x = fabsf(v.x); o.y = fabsf(v.y);
            o.z = fabsf(v.z); o.w = fabsf(v.w);
            reinterpret_cast<float4*>(out)[n] = o;
        } else {
            float4 ns = reinterpret_cast<float4*>(g_ns)[n];
            float4 rs;
            rs.x = ns.x * v.x; rs.y = ns.y * v.y;
            rs.z = ns.z * v.z; rs.w = ns.w * v.w;
            reinterpret_cast<float4*>(g_rs)[n] = rs;
            reinterpret_cast<float4*>(g_acc)[n] = make_float4(0.f, 0.f, 0.f, 0.f);
        }
    }
}

extern "C" void kernel_launch(void* const* d_in, const int* in_sizes, int n_in,
                              void* d_out, int out_size) {
    // Layout A (dict order): x, src, dst, W0,b0..W5,b5
    // Layout B (sorted):     W0..W5, b0..b5, dst, src, x
    const float *x, *W0, *b0, *W1, *b1, *W2, *b2, *W3, *b3, *W4, *b4, *W5, *b5;
    const void *src, *dst;

    if (in_sizes[0] == NN) {
        x   = (const float*)d_in[0];
        src = d_in[1];
        dst = d_in[2];
        W0 = (const float*)d_in[3];  b0 = (const float*)d_in[4];
        W1 = (const float*)d_in[5];  b1 = (const float*)d_in[6];
        W2 = (const float*)d_in[7];  b2 = (const float*)d_in[8];
        W3 = (const float*)d_in[9];  b3 = (const float*)d_in[10];
        W4 = (const float*)d_in[11]; b4 = (const float*)d_in[12];
        W5 = (const float*)d_in[13]; b5 = (const float*)d_in[14];
    } else {
        W0 = (const float*)d_in[0];  W1 = (const float*)d_in[1];
        W2 = (const float*)d_in[2];  W3 = (const float*)d_in[3];
        W4 = (const float*)d_in[4];  W5 = (const float*)d_in[5];
        b0 = (const float*)d_in[6];  b1 = (const float*)d_in[7];
        b2 = (const float*)d_in[8];  b3 = (const float*)d_in[9];
        b4 = (const float*)d_in[10]; b5 = (const float*)d_in[11];
        dst = d_in[12];
        src = d_in[13];
        x   = (const float*)d_in[14];
    }
    float* out = (float*)d_out;

    const int TB  = 256;
    const int GZ  = NPAD / 4 / TB + 2;            // setup: 98 zero blocks + 2
    const int GN4 = (NN / 4 + TB - 1) / TB;       // 98
    const int GE  = (EE + TB - 1) / TB;           // 6250
    const int GS2 = (EE / 2 + TB - 1) / TB;       // 3125

    k_setup<<<GZ, TB>>>((const unsigned long long*)src,
                        W0, b0, W1, b1, W2, b2, W3, b3, W4, b4, W5, b5);
    k_edges<<<GE, TB>>>(src, dst);
    k_scan<<<98, TB>>>();
    k_permInit<<<GE + GN4, TB>>>(GE, x);

    for (int k = 0; k < 6; k++) {
        k_scatter<<<GS2, TB>>>();
        k_post<<<GN4, TB>>>(k, out);
    }
}